// round 5
// baseline (speedup 1.0000x reference)
#include <cuda_runtime.h>
#include <cuda_bf16.h>
#include <cstdint>

#define NUM_GRAPHS 2048
#define DIM 256
#define HN 32
#define HG 64

typedef unsigned int u32;

// ---- smem layout (bytes) ----
#define SM_XH 0u          // X hi  [256 r][64 k] bf16, SW128  (32768)
#define SM_XL 32768u      // X lo                              (32768)
#define SM_WH 65536u      // W^T hi [32 n][264 k] bf16 pad8    (16896)
#define SM_WL 82432u      // W^T lo                            (16896)
#define SM_SCR 99328u     // scratch 128 x 4 float4            (8192)
#define SM_GS 107520u     // graph sums 4 x 256 f32            (4096)
#define SMEM_BYTES 111616
#define WROW 528          // bytes per W^T row (264 bf16)

__device__ __forceinline__ u32 smem_u32(const void* p) {
    u32 a;
    asm("{ .reg .u64 t; cvta.to.shared.u64 t, %1; cvt.u32.u64 %0, t; }" : "=r"(a) : "l"(p));
    return a;
}
__device__ __forceinline__ void ldsm4(u32& r0, u32& r1, u32& r2, u32& r3, u32 a) {
    asm volatile("ldmatrix.sync.aligned.m8n8.x4.shared.b16 {%0,%1,%2,%3}, [%4];"
        : "=r"(r0), "=r"(r1), "=r"(r2), "=r"(r3) : "r"(a));
}
__device__ __forceinline__ void mma16816(float* d, u32 a0, u32 a1, u32 a2, u32 a3,
                                         u32 b0, u32 b1) {
    asm volatile("mma.sync.aligned.m16n8k16.row.col.f32.bf16.bf16.f32 "
        "{%0,%1,%2,%3}, {%4,%5,%6,%7}, {%8,%9}, {%0,%1,%2,%3};"
        : "+f"(d[0]), "+f"(d[1]), "+f"(d[2]), "+f"(d[3])
        : "r"(a0), "r"(a1), "r"(a2), "r"(a3), "r"(b0), "r"(b1));
}
__device__ __forceinline__ u32 bits2(__nv_bfloat162 v) {
    u32 r; __builtin_memcpy(&r, &v, 4); return r;
}
__device__ __forceinline__ void split2(float x0, float x1, u32& hp, u32& lp) {
    __nv_bfloat162 h = __float22bfloat162_rn(make_float2(x0, x1));
    float2 f = __bfloat1622float2(h);
    __nv_bfloat162 l = __float22bfloat162_rn(make_float2(x0 - f.x, x1 - f.y));
    hp = bits2(h); lp = bits2(l);
}
__device__ __forceinline__ float4 shfl16_add(float4 a) {
    a.x += __shfl_xor_sync(0xffffffffu, a.x, 16);
    a.y += __shfl_xor_sync(0xffffffffu, a.y, 16);
    a.z += __shfl_xor_sync(0xffffffffu, a.z, 16);
    a.w += __shfl_xor_sync(0xffffffffu, a.w, 16);
    return a;
}

// ---------------------------------------------------------------------------
// Fused kernel: CTA = 256 nodes = 4 graphs. grid 512, 256 threads, 2 CTAs/SM.
//   node_out = X @ Wn   (bf16 hi/lo 3-term mma.sync, fp32 accum)
//   graph_out = mean(X per graph) @ Wg + b   (fp32, smem-staged epilogue)
// ---------------------------------------------------------------------------
__global__ __launch_bounds__(256, 2) void k_fused(
    const float* __restrict__ X, const float* __restrict__ Wn,
    const float* __restrict__ Wg, const float* __restrict__ bg,
    float* __restrict__ graph_out, float* __restrict__ node_out)
{
    extern __shared__ char smem[];
    const u32 sbase = smem_u32(smem);
    float4* scr = (float4*)(smem + SM_SCR);
    float*  gs  = (float*)(smem + SM_GS);

    const int t = threadIdx.x;
    const int w = t >> 5;
    const int lane = t & 31;
    const long tileRow = (long)blockIdx.x * 256;

    // ---- stage W^T hi/lo : Wn[256][32] f32 -> [n][264k] bf16 (pad rows) ----
    {
        const float4* W4 = (const float4*)Wn;
#pragma unroll
        for (int i = 0; i < 8; i++) {
            int idx = t + 256 * i;       // 2048 float4
            float4 v = W4[idx];
            int d = idx >> 3;            // k dim 0..255
            int n0 = (idx & 7) * 4;
            float vv[4] = {v.x, v.y, v.z, v.w};
#pragma unroll
            for (int j = 0; j < 4; j++) {
                __nv_bfloat16 h = __float2bfloat16_rn(vv[j]);
                float rsd = vv[j] - __bfloat162float(h);
                __nv_bfloat16 l = __float2bfloat16_rn(rsd);
                u32 off = (u32)(n0 + j) * WROW + (u32)d * 2;
                *(__nv_bfloat16*)(smem + SM_WH + off) = h;
                *(__nv_bfloat16*)(smem + SM_WL + off) = l;
            }
        }
    }

    // fragment address precompute
    const int aq = lane >> 3;
    const int ai = lane & 7;
    const u32 amask = (u32)ai << 4;            // SW128 xor key
    const u32 akb = (u32)(aq >> 1) * 16;
    const u32 arow0 = (u32)(w * 32 + ((aq & 1) ? 8 : 0) + ai) * 128;
    const u32 bbase = (u32)(aq * 8 + ai) * WROW;

    float acc[2][4][4];
#pragma unroll
    for (int mt = 0; mt < 2; mt++)
#pragma unroll
        for (int nt = 0; nt < 4; nt++)
#pragma unroll
            for (int e = 0; e < 4; e++) acc[mt][nt][e] = 0.f;

    const float4* X4 = (const float4*)X;
    const int r0 = t >> 4;       // staging row base 0..15
    const int c4 = t & 15;       // staging float4 column

#pragma unroll 1
    for (int ch = 0; ch < 4; ch++) {
        __syncthreads();   // prior chunk's smem reads done (covers W staging on ch0)

        // ---- stage X chunk [256 r][64 k]: hi/lo bf16, SW128; graph partials ----
        float4 part[4];
#pragma unroll
        for (int g = 0; g < 4; g++) part[g] = make_float4(0.f, 0.f, 0.f, 0.f);

#pragma unroll 1
        for (int half = 0; half < 2; half++) {
            float4 v[8];
#pragma unroll
            for (int i2 = 0; i2 < 8; i2++) {
                int r = r0 + 16 * (half * 8 + i2);
                v[i2] = X4[(tileRow + r) * 64 + ch * 16 + c4];
            }
#pragma unroll
            for (int i2 = 0; i2 < 8; i2++) {
                int i = half * 8 + i2;
                int r = r0 + 16 * i;
                uint2 hp, lp;
                split2(v[i2].x, v[i2].y, hp.x, lp.x);
                split2(v[i2].z, v[i2].w, hp.y, lp.y);
                u32 off = (u32)r * 128u + (((u32)c4 * 8u) ^ (((u32)r & 7u) << 4));
                *(uint2*)(smem + SM_XH + off) = hp;
                *(uint2*)(smem + SM_XL + off) = lp;
                int g = i >> 2;
                part[g].x += v[i2].x; part[g].y += v[i2].y;
                part[g].z += v[i2].z; part[g].w += v[i2].w;
            }
        }
        // pair-reduce (r0, r0^1) via shfl, lanes with bit4==0 store
        {
#pragma unroll
            for (int g = 0; g < 4; g++) part[g] = shfl16_add(part[g]);
            if (!(t & 16)) {
                int base = ((t >> 5) * 16 + (t & 15)) * 4;
#pragma unroll
                for (int g = 0; g < 4; g++) scr[base + g] = part[g];
            }
        }
        __syncthreads();

        // ---- graph column-sum reduce (first 64 threads, overlaps MMA) ----
        if (t < 64) {
            int cc = t & 15, g = t >> 4;
            float4 a = scr[(0 * 16 + cc) * 4 + g];
#pragma unroll
            for (int pr = 1; pr < 8; pr++) {
                float4 b = scr[(pr * 16 + cc) * 4 + g];
                a.x += b.x; a.y += b.y; a.z += b.z; a.w += b.w;
            }
            *(float4*)&gs[g * 256 + ch * 64 + cc * 4] = a;
        }

        // ---- compute: 4 k16-steps ----
#pragma unroll
        for (int ks = 0; ks < 4; ks++) {
            const u32 koff = ((u32)ks * 32 + akb) ^ amask;
            u32 ah[2][4], al[2][4];
            ldsm4(ah[0][0], ah[0][1], ah[0][2], ah[0][3], sbase + SM_XH + arow0 + koff);
            ldsm4(ah[1][0], ah[1][1], ah[1][2], ah[1][3], sbase + SM_XH + arow0 + 2048 + koff);
            ldsm4(al[0][0], al[0][1], al[0][2], al[0][3], sbase + SM_XL + arow0 + koff);
            ldsm4(al[1][0], al[1][1], al[1][2], al[1][3], sbase + SM_XL + arow0 + 2048 + koff);

            const u32 bko = (u32)(ch * 64 + ks * 16) * 2;
            u32 bh0[4], bh1[4], bl0[4], bl1[4];
            ldsm4(bh0[0], bh0[1], bh0[2], bh0[3], sbase + SM_WH + bbase + bko);
            ldsm4(bh1[0], bh1[1], bh1[2], bh1[3], sbase + SM_WH + bbase + bko + 16);
            ldsm4(bl0[0], bl0[1], bl0[2], bl0[3], sbase + SM_WL + bbase + bko);
            ldsm4(bl1[0], bl1[1], bl1[2], bl1[3], sbase + SM_WL + bbase + bko + 16);

#pragma unroll
            for (int mt = 0; mt < 2; mt++)
#pragma unroll
                for (int nt = 0; nt < 4; nt++) {
                    mma16816(acc[mt][nt], ah[mt][0], ah[mt][1], ah[mt][2], ah[mt][3],
                             bh0[nt], bh1[nt]);
                    mma16816(acc[mt][nt], ah[mt][0], ah[mt][1], ah[mt][2], ah[mt][3],
                             bl0[nt], bl1[nt]);
                    mma16816(acc[mt][nt], al[mt][0], al[mt][1], al[mt][2], al[mt][3],
                             bh0[nt], bh1[nt]);
                }
        }
    }

    // ---- node_out epilogue ----
    {
        const int rr = lane >> 2;
        const int cc = (lane & 3) * 2;
#pragma unroll
        for (int mt = 0; mt < 2; mt++) {
            long r = tileRow + w * 32 + mt * 16 + rr;
#pragma unroll
            for (int nt = 0; nt < 4; nt++) {
                float* dd = acc[mt][nt];
                int c0 = nt * 8 + cc;
                *(float2*)(node_out + r * HN + c0) = make_float2(dd[0], dd[1]);
                *(float2*)(node_out + (r + 8) * HN + c0) = make_float2(dd[2], dd[3]);
            }
        }
    }

    // ---- graph head: stage Wg into (reused) X smem, then dot ----
    __syncthreads();
    {
        const float4* Wg4 = (const float4*)Wg;
        float4* Wd = (float4*)smem;          // aliases XH/XL (64 KB)
#pragma unroll
        for (int i = 0; i < 16; i++) Wd[t + 256 * i] = Wg4[t + 256 * i];
    }
    __syncthreads();
    {
        const float* Wgs = (const float*)smem;   // [256 d][64 j]
        const int g = t >> 6;
        const int j = t & 63;
        const float* gsg = gs + g * 256;
        float s = 0.f;
#pragma unroll 8
        for (int d = 0; d < 256; d++)
            s += gsg[d] * Wgs[d * 64 + j];
        graph_out[(blockIdx.x * 4 + g) * HG + j] = s * (1.0f / 64.0f) + __ldg(bg + j);
    }
}

// ---------------------------------------------------------------------------
extern "C" void kernel_launch(void* const* d_in, const int* in_sizes, int n_in,
                              void* d_out, int out_size) {
    const float* X  = (const float*)d_in[0];
    // d_in[1] = batch (int32): 64 consecutive nodes per graph, implicit
    const float* Wg = (const float*)d_in[2];
    const float* bg = (const float*)d_in[3];
    const float* Wn = (const float*)d_in[4];
    float* out = (float*)d_out;
    (void)in_sizes; (void)n_in; (void)out_size;

    cudaFuncSetAttribute(k_fused, cudaFuncAttributeMaxDynamicSharedMemorySize, SMEM_BYTES);

    // output layout: graph_out [2048*64] first, then node_out [131072*32]
    k_fused<<<512, 256, SMEM_BYTES>>>(X, Wn, Wg, bg, out, out + NUM_GRAPHS * HG);
}

// round 6
// speedup vs baseline: 1.0155x; 1.0155x over previous
#include <cuda_runtime.h>
#include <cuda_bf16.h>
#include <cstdint>

#define NUM_GRAPHS 2048
#define DIM 256
#define HN 32
#define HG 64

typedef unsigned int u32;

// ---- smem layout (bytes) ----
#define SM_XH 0u          // X hi  [128 r][64 k] bf16, SW128   (16384)
#define SM_XL 16384u      // X lo                               (16384)
#define SM_WH 32768u      // W^T hi [32 n][264 k] bf16 pad8     (16896)
#define SM_WL 49664u      // W^T lo                             (16896)
#define SM_SCR 66560u     // scratch 128 x 2 float4             (4096)
#define SM_GS 70656u      // graph sums 2 x 256 f32             (2048)
#define SMEM_BYTES 72704
#define WROW 528          // bytes per W^T row (264 bf16)

__device__ __forceinline__ u32 smem_u32(const void* p) {
    u32 a;
    asm("{ .reg .u64 t; cvta.to.shared.u64 t, %1; cvt.u32.u64 %0, t; }" : "=r"(a) : "l"(p));
    return a;
}
__device__ __forceinline__ void ldsm4(u32& r0, u32& r1, u32& r2, u32& r3, u32 a) {
    asm volatile("ldmatrix.sync.aligned.m8n8.x4.shared.b16 {%0,%1,%2,%3}, [%4];"
        : "=r"(r0), "=r"(r1), "=r"(r2), "=r"(r3) : "r"(a));
}
__device__ __forceinline__ void mma16816(float* d, u32 a0, u32 a1, u32 a2, u32 a3,
                                         u32 b0, u32 b1) {
    asm volatile("mma.sync.aligned.m16n8k16.row.col.f32.bf16.bf16.f32 "
        "{%0,%1,%2,%3}, {%4,%5,%6,%7}, {%8,%9}, {%0,%1,%2,%3};"
        : "+f"(d[0]), "+f"(d[1]), "+f"(d[2]), "+f"(d[3])
        : "r"(a0), "r"(a1), "r"(a2), "r"(a3), "r"(b0), "r"(b1));
}
__device__ __forceinline__ u32 bits2(__nv_bfloat162 v) {
    u32 r; __builtin_memcpy(&r, &v, 4); return r;
}
// hi = truncate-to-bf16 (exact, PRMT-packed); lo = rn_bf16(x - hi)
__device__ __forceinline__ void split2(float x0, float x1, u32& hp, u32& lp) {
    u32 u0 = __float_as_uint(x0), u1 = __float_as_uint(x1);
    asm("prmt.b32 %0, %1, %2, 0x7632;" : "=r"(hp) : "r"(u0), "r"(u1));
    float h0 = __uint_as_float(u0 & 0xFFFF0000u);
    float h1 = __uint_as_float(u1 & 0xFFFF0000u);
    lp = bits2(__float22bfloat162_rn(make_float2(x0 - h0, x1 - h1)));
}

// ---------------------------------------------------------------------------
// Fused kernel: CTA = 128 nodes = 2 graphs. grid 1024, 128 threads, 3 CTAs/SM.
//   node_out = X @ Wn   (bf16 hi/lo 3-term mma.sync, fp32 accum)
//   graph_out = mean(X per graph) @ Wg + b   (fp32, smem-staged epilogue)
// X chunk n+1 LDGs issued before chunk-n MMA (latency hidden).
// ---------------------------------------------------------------------------
__global__ __launch_bounds__(128, 3) void k_fused(
    const float* __restrict__ X, const float* __restrict__ Wn,
    const float* __restrict__ Wg, const float* __restrict__ bg,
    float* __restrict__ graph_out, float* __restrict__ node_out)
{
    extern __shared__ char smem[];
    const u32 sbase = smem_u32(smem);
    float4* scr = (float4*)(smem + SM_SCR);
    float*  gsum = (float*)(smem + SM_GS);

    const int t = threadIdx.x;
    const int w = t >> 5;
    const int lane = t & 31;
    const long tileRow = (long)blockIdx.x * 128;

    // ---- stage W^T hi/lo : Wn[256][32] f32 -> [n][264k] bf16 (pad rows) ----
    {
        const float4* W4 = (const float4*)Wn;
#pragma unroll
        for (int i = 0; i < 16; i++) {
            int idx = t + 128 * i;       // 2048 float4
            float4 v = W4[idx];
            int d = idx >> 3;            // k dim 0..255
            int n0 = (idx & 7) * 4;
            float vv[4] = {v.x, v.y, v.z, v.w};
#pragma unroll
            for (int j = 0; j < 4; j++) {
                __nv_bfloat16 h = __float2bfloat16_rz(vv[j]);   // truncation (matches X split)
                float rsd = vv[j] - __bfloat162float(h);
                __nv_bfloat16 l = __float2bfloat16_rn(rsd);
                u32 off = (u32)(n0 + j) * WROW + (u32)d * 2;
                *(__nv_bfloat16*)(smem + SM_WH + off) = h;
                *(__nv_bfloat16*)(smem + SM_WL + off) = l;
            }
        }
        // zero graph-sum accumulator (128 thr x 4 floats = 512 = 2*256)
        *(float4*)&gsum[t * 4] = make_float4(0.f, 0.f, 0.f, 0.f);
    }

    // fragment address precompute
    const int aq = lane >> 3;
    const int ai = lane & 7;
    const u32 amask = (u32)ai << 4;            // SW128 xor key
    const u32 akb = (u32)(aq >> 1) * 16;
    const u32 arow0 = (u32)(w * 32 + ((aq & 1) ? 8 : 0) + ai) * 128;
    const u32 bbase = (u32)(aq * 8 + ai) * WROW;

    float acc[2][4][4];
#pragma unroll
    for (int mt = 0; mt < 2; mt++)
#pragma unroll
        for (int nt = 0; nt < 4; nt++)
#pragma unroll
            for (int e = 0; e < 4; e++) acc[mt][nt][e] = 0.f;

    // per-thread staging geometry: rows r0+8i (i=0..15), fixed float4 column c4
    const int r0 = t >> 4;
    const int c4 = t & 15;
    const float4* xp = (const float4*)X + (tileRow + r0) * 64 + c4;

    // prologue: prefetch chunk 0
    float4 v[16];
#pragma unroll
    for (int i = 0; i < 16; i++) v[i] = xp[i * 512];

#pragma unroll 1
    for (int ch = 0; ch < 4; ch++) {
        __syncthreads();   // prior chunk's smem reads done (covers W staging on ch0)

        // ---- convert + store chunk [128 r][64 k] hi/lo, SW128; graph partials ----
        float4 p0 = make_float4(0.f, 0.f, 0.f, 0.f);
        float4 p1 = make_float4(0.f, 0.f, 0.f, 0.f);
        {
            const u32 cbase = (((u32)c4 * 8u) ^ (((u32)r0 & 7u) << 4));
#pragma unroll
            for (int i = 0; i < 16; i++) {
                int r = r0 + 8 * i;
                uint2 hp, lp;
                split2(v[i].x, v[i].y, hp.x, lp.x);
                split2(v[i].z, v[i].w, hp.y, lp.y);
                u32 off = (u32)r * 128u + cbase;   // (r&7)==（r0&7) for all i
                *(uint2*)(smem + SM_XH + off) = hp;
                *(uint2*)(smem + SM_XL + off) = lp;
                if (i < 8) { p0.x += v[i].x; p0.y += v[i].y; p0.z += v[i].z; p0.w += v[i].w; }
                else       { p1.x += v[i].x; p1.y += v[i].y; p1.z += v[i].z; p1.w += v[i].w; }
            }
        }
        scr[t * 2 + 0] = p0;
        scr[t * 2 + 1] = p1;
        __syncthreads();

        // ---- prefetch next chunk (hidden behind MMA below) ----
        if (ch < 3) {
#pragma unroll
            for (int i = 0; i < 16; i++) v[i] = xp[i * 512 + (ch + 1) * 16];
        }

        // ---- graph column-sum reduce (warp 0, overlaps MMA of warps 1-3) ----
        if (t < 32) {
            int cc = t & 15, g = t >> 4;
            float4 a = scr[cc * 2 + g];
#pragma unroll
            for (int rb = 1; rb < 8; rb++) {
                float4 b = scr[(cc + 16 * rb) * 2 + g];
                a.x += b.x; a.y += b.y; a.z += b.z; a.w += b.w;
            }
            float4* gp = (float4*)&gsum[g * 256 + ch * 64 + cc * 4];
            float4 cur = gp[0];
            cur.x += a.x; cur.y += a.y; cur.z += a.z; cur.w += a.w;
            gp[0] = cur;
        }

        // ---- compute: 4 k16-steps ----
#pragma unroll
        for (int ks = 0; ks < 4; ks++) {
            const u32 koff = ((u32)ks * 32 + akb) ^ amask;
            u32 ah[2][4], al[2][4];
            ldsm4(ah[0][0], ah[0][1], ah[0][2], ah[0][3], sbase + SM_XH + arow0 + koff);
            ldsm4(ah[1][0], ah[1][1], ah[1][2], ah[1][3], sbase + SM_XH + arow0 + 2048 + koff);
            ldsm4(al[0][0], al[0][1], al[0][2], al[0][3], sbase + SM_XL + arow0 + koff);
            ldsm4(al[1][0], al[1][1], al[1][2], al[1][3], sbase + SM_XL + arow0 + 2048 + koff);

            const u32 bko = (u32)(ch * 64 + ks * 16) * 2;
            u32 bh0[4], bh1[4], bl0[4], bl1[4];
            ldsm4(bh0[0], bh0[1], bh0[2], bh0[3], sbase + SM_WH + bbase + bko);
            ldsm4(bh1[0], bh1[1], bh1[2], bh1[3], sbase + SM_WH + bbase + bko + 16);
            ldsm4(bl0[0], bl0[1], bl0[2], bl0[3], sbase + SM_WL + bbase + bko);
            ldsm4(bl1[0], bl1[1], bl1[2], bl1[3], sbase + SM_WL + bbase + bko + 16);

#pragma unroll
            for (int mt = 0; mt < 2; mt++)
#pragma unroll
                for (int nt = 0; nt < 4; nt++) {
                    mma16816(acc[mt][nt], ah[mt][0], ah[mt][1], ah[mt][2], ah[mt][3],
                             bh0[nt], bh1[nt]);
                    mma16816(acc[mt][nt], ah[mt][0], ah[mt][1], ah[mt][2], ah[mt][3],
                             bl0[nt], bl1[nt]);
                    mma16816(acc[mt][nt], al[mt][0], al[mt][1], al[mt][2], al[mt][3],
                             bh0[nt], bh1[nt]);
                }
        }
    }

    // ---- node_out epilogue ----
    {
        const int rr = lane >> 2;
        const int cc = (lane & 3) * 2;
#pragma unroll
        for (int mt = 0; mt < 2; mt++) {
            long r = tileRow + w * 32 + mt * 16 + rr;
#pragma unroll
            for (int nt = 0; nt < 4; nt++) {
                float* dd = acc[mt][nt];
                int c0 = nt * 8 + cc;
                *(float2*)(node_out + r * HN + c0) = make_float2(dd[0], dd[1]);
                *(float2*)(node_out + (r + 8) * HN + c0) = make_float2(dd[2], dd[3]);
            }
        }
    }

    // ---- graph head: stage Wg (64 KB) into dead X/W smem, then dot ----
    __syncthreads();
    {
        const float4* Wg4 = (const float4*)Wg;
        float4* Wd = (float4*)smem;          // overlays XH..WL (66 KB avail)
#pragma unroll
        for (int i = 0; i < 32; i++) Wd[t + 128 * i] = Wg4[t + 128 * i];
    }
    __syncthreads();
    {
        const float* Wgs = (const float*)smem;   // [256 d][64 j]
        const int g = t >> 6;
        const int j = t & 63;
        const float* gsg = gsum + g * 256;
        float s = 0.f;
#pragma unroll 8
        for (int d = 0; d < 256; d++)
            s += gsg[d] * Wgs[d * 64 + j];
        graph_out[(blockIdx.x * 2 + g) * HG + j] = s * (1.0f / 64.0f) + __ldg(bg + j);
    }
}

// ---------------------------------------------------------------------------
extern "C" void kernel_launch(void* const* d_in, const int* in_sizes, int n_in,
                              void* d_out, int out_size) {
    const float* X  = (const float*)d_in[0];
    // d_in[1] = batch (int32): 64 consecutive nodes per graph, implicit
    const float* Wg = (const float*)d_in[2];
    const float* bg = (const float*)d_in[3];
    const float* Wn = (const float*)d_in[4];
    float* out = (float*)d_out;
    (void)in_sizes; (void)n_in; (void)out_size;

    cudaFuncSetAttribute(k_fused, cudaFuncAttributeMaxDynamicSharedMemorySize, SMEM_BYTES);

    // output layout: graph_out [2048*64] first, then node_out [131072*32]
    k_fused<<<1024, 128, SMEM_BYTES>>>(X, Wn, Wg, bg, out, out + NUM_GRAPHS * HG);
}

// round 7
// speedup vs baseline: 1.0300x; 1.0143x over previous
#include <cuda_runtime.h>
#include <cuda_bf16.h>
#include <cstdint>

#define NUM_GRAPHS 2048
#define DIM 256
#define HN 32
#define HG 64

typedef unsigned int u32;

// ---- smem layout (bytes) ----
// X buffers: 2 x { hi 8192, lo 8192 }  [128 r][32 k] bf16, custom swizzle
#define SM_BUF(b)  ((u32)(b) * 16384u)
#define SM_WH 32768u      // W^T hi [32 n][264 k] bf16 pad8  (16896)
#define SM_WL 49664u      // W^T lo                           (16896)
#define SM_SCR0 66560u    // scratch buf0: 128 x 2 float4     (4096)
#define SM_SCR1 70656u    // scratch buf1                      (4096)
#define SM_GS 74752u      // graph sums 2 x 256 f32            (2048)
#define SMEM_BYTES 76800
#define WROW 528          // bytes per W^T row (264 bf16)

__device__ __forceinline__ u32 smem_u32(const void* p) {
    u32 a;
    asm("{ .reg .u64 t; cvta.to.shared.u64 t, %1; cvt.u32.u64 %0, t; }" : "=r"(a) : "l"(p));
    return a;
}
__device__ __forceinline__ void ldsm4(u32& r0, u32& r1, u32& r2, u32& r3, u32 a) {
    asm volatile("ldmatrix.sync.aligned.m8n8.x4.shared.b16 {%0,%1,%2,%3}, [%4];"
        : "=r"(r0), "=r"(r1), "=r"(r2), "=r"(r3) : "r"(a));
}
__device__ __forceinline__ void mma16816(float* d, u32 a0, u32 a1, u32 a2, u32 a3,
                                         u32 b0, u32 b1) {
    asm volatile("mma.sync.aligned.m16n8k16.row.col.f32.bf16.bf16.f32 "
        "{%0,%1,%2,%3}, {%4,%5,%6,%7}, {%8,%9}, {%0,%1,%2,%3};"
        : "+f"(d[0]), "+f"(d[1]), "+f"(d[2]), "+f"(d[3])
        : "r"(a0), "r"(a1), "r"(a2), "r"(a3), "r"(b0), "r"(b1));
}
__device__ __forceinline__ u32 bits2(__nv_bfloat162 v) {
    u32 r; __builtin_memcpy(&r, &v, 4); return r;
}
// hi = truncate-to-bf16 (exact, PRMT-packed); lo = rn_bf16(x - hi)
__device__ __forceinline__ void split2(float x0, float x1, u32& hp, u32& lp) {
    u32 u0 = __float_as_uint(x0), u1 = __float_as_uint(x1);
    asm("prmt.b32 %0, %1, %2, 0x7632;" : "=r"(hp) : "r"(u0), "r"(u1));
    float h0 = __uint_as_float(u0 & 0xFFFF0000u);
    float h1 = __uint_as_float(u1 & 0xFFFF0000u);
    lp = bits2(__float22bfloat162_rn(make_float2(x0 - h0, x1 - h1)));
}

// ---------------------------------------------------------------------------
// Fused kernel: CTA = 128 nodes = 2 graphs. grid 1024, 128 threads, 3 CTAs/SM.
// K pipelined in 8 chunks of 32 with double-buffered X smem:
//   stage(ch) -> LDG(ch+1) -> sync -> reduce -> MMA(ch)
// ---------------------------------------------------------------------------
__global__ __launch_bounds__(128, 3) void k_fused(
    const float* __restrict__ X, const float* __restrict__ Wn,
    const float* __restrict__ Wg, const float* __restrict__ bg,
    float* __restrict__ graph_out, float* __restrict__ node_out)
{
    extern __shared__ char smem[];
    const u32 sbase = smem_u32(smem);
    float4* scr[2] = { (float4*)(smem + SM_SCR0), (float4*)(smem + SM_SCR1) };
    float*  gsum = (float*)(smem + SM_GS);

    const int t = threadIdx.x;
    const int w = t >> 5;
    const int lane = t & 31;
    const long tileRow = (long)blockIdx.x * 128;

    // ---- stage W^T hi/lo : Wn[256][32] f32 -> [n][264k] bf16 (pad rows) ----
    {
        const float4* W4 = (const float4*)Wn;
#pragma unroll
        for (int i = 0; i < 16; i++) {
            int idx = t + 128 * i;       // 2048 float4
            float4 v = W4[idx];
            int d = idx >> 3;            // k dim 0..255
            int n0 = (idx & 7) * 4;
            float vv[4] = {v.x, v.y, v.z, v.w};
#pragma unroll
            for (int j = 0; j < 4; j++) {
                __nv_bfloat16 h = __float2bfloat16_rz(vv[j]);   // truncation (matches X split)
                float rsd = vv[j] - __bfloat162float(h);
                __nv_bfloat16 l = __float2bfloat16_rn(rsd);
                u32 off = (u32)(n0 + j) * WROW + (u32)d * 2;
                *(__nv_bfloat16*)(smem + SM_WH + off) = h;
                *(__nv_bfloat16*)(smem + SM_WL + off) = l;
            }
        }
    }

    // ---- fragment address precompute ----
    const int aq = lane >> 3;
    const int ai = lane & 7;
    // A: row-pair packed layout: addr = (r>>1)*128 + (r&1)*64 + kq*16,
    //    swizzled by key ((r>>1)&7)<<4.  kq selected by (aq>>1) and ks.
    u32 rb[2];
#pragma unroll
    for (int mt = 0; mt < 2; mt++) {
        int r = w * 32 + mt * 16 + ((aq & 1) ? 8 : 0) + ai;
        rb[mt] = ((u32)(r >> 1) * 128u + (u32)(r & 1) * 64u) ^ ((((u32)r >> 1) & 7u) << 4);
    }
    const u32 kqsel = (u32)(aq >> 1) << 4;
    const u32 bbase = (u32)(aq * 8 + ai) * WROW;

    float acc[2][4][4];
#pragma unroll
    for (int mt = 0; mt < 2; mt++)
#pragma unroll
        for (int nt = 0; nt < 4; nt++)
#pragma unroll
            for (int e = 0; e < 4; e++) acc[mt][nt][e] = 0.f;

    // ---- staging geometry: thread handles rows rsub+16i (i=0..7), col quad c4 ----
    const int rsub = t >> 3;     // 0..15
    const int c4 = t & 7;        // float4 within K32 row
    const float4* xp = (const float4*)X + (tileRow + rsub) * 64 + c4;
    // STS offset: key ((rsub>>1)&7) constant across i (row step 16 -> key step 8 ≡ 0 mod 8)
    const u32 sts_off = (((u32)(rsub >> 1) * 128u + (u32)(rsub & 1) * 64u)
                         ^ ((((u32)rsub >> 1) & 7u) << 4)) ^ ((u32)c4 << 3);

    // prologue: LDG chunk 0
    float4 v[8];
#pragma unroll
    for (int i = 0; i < 8; i++) v[i] = xp[i * 1024];

#pragma unroll 1
    for (int ch = 0; ch < 8; ch++) {
        const int b = ch & 1;
        const u32 hbuf = SM_BUF(b);

        // ---- convert + STS chunk ch; fp32 graph partials ----
        float4 p0 = make_float4(0.f, 0.f, 0.f, 0.f);
        float4 p1 = make_float4(0.f, 0.f, 0.f, 0.f);
#pragma unroll
        for (int i = 0; i < 8; i++) {
            uint2 hp, lp;
            split2(v[i].x, v[i].y, hp.x, lp.x);
            split2(v[i].z, v[i].w, hp.y, lp.y);
            u32 off = sts_off + (u32)i * 1024u;
            *(uint2*)(smem + hbuf + off) = hp;
            *(uint2*)(smem + hbuf + 8192u + off) = lp;
            if (i < 4) { p0.x += v[i].x; p0.y += v[i].y; p0.z += v[i].z; p0.w += v[i].w; }
            else       { p1.x += v[i].x; p1.y += v[i].y; p1.z += v[i].z; p1.w += v[i].w; }
        }
        scr[b][t * 2 + 0] = p0;
        scr[b][t * 2 + 1] = p1;

        // ---- issue LDGs for chunk ch+1 (latency hidden by sync + MMA) ----
        if (ch < 7) {
#pragma unroll
            for (int i = 0; i < 8; i++) v[i] = xp[i * 1024 + (ch + 1) * 8];
        }

        __syncthreads();   // STS(ch) visible; buffers alternate so MMA(ch-1) safe

        // ---- graph column-sum reduce (16 threads, overlaps others' MMA) ----
        if (t < 16) {
            int g = t >> 3, cc = t & 7;
            float4 a = scr[b][cc * 2 + g];
#pragma unroll
            for (int j = 1; j < 16; j++) {
                float4 x2 = scr[b][(8 * j + cc) * 2 + g];
                a.x += x2.x; a.y += x2.y; a.z += x2.z; a.w += x2.w;
            }
            *(float4*)&gsum[g * 256 + ch * 32 + cc * 4] = a;
        }

        // ---- MMA on buffer b: 2 k16-steps ----
#pragma unroll
        for (int ks = 0; ks < 2; ks++) {
            const u32 kx = ((u32)ks << 5) ^ kqsel;
            u32 ah[2][4], al[2][4];
            ldsm4(ah[0][0], ah[0][1], ah[0][2], ah[0][3], sbase + hbuf + (rb[0] ^ kx));
            ldsm4(ah[1][0], ah[1][1], ah[1][2], ah[1][3], sbase + hbuf + (rb[1] ^ kx));
            ldsm4(al[0][0], al[0][1], al[0][2], al[0][3], sbase + hbuf + 8192u + (rb[0] ^ kx));
            ldsm4(al[1][0], al[1][1], al[1][2], al[1][3], sbase + hbuf + 8192u + (rb[1] ^ kx));

            const u32 bko = (u32)(ch * 2 + ks) << 5;   // k16-step * 32 bytes
            u32 bh0[4], bh1[4], bl0[4], bl1[4];
            ldsm4(bh0[0], bh0[1], bh0[2], bh0[3], sbase + SM_WH + bbase + bko);
            ldsm4(bh1[0], bh1[1], bh1[2], bh1[3], sbase + SM_WH + bbase + bko + 16);
            ldsm4(bl0[0], bl0[1], bl0[2], bl0[3], sbase + SM_WL + bbase + bko);
            ldsm4(bl1[0], bl1[1], bl1[2], bl1[3], sbase + SM_WL + bbase + bko + 16);

#pragma unroll
            for (int mt = 0; mt < 2; mt++)
#pragma unroll
                for (int nt = 0; nt < 4; nt++) {
                    mma16816(acc[mt][nt], ah[mt][0], ah[mt][1], ah[mt][2], ah[mt][3],
                             bh0[nt], bh1[nt]);
                    mma16816(acc[mt][nt], ah[mt][0], ah[mt][1], ah[mt][2], ah[mt][3],
                             bl0[nt], bl1[nt]);
                    mma16816(acc[mt][nt], al[mt][0], al[mt][1], al[mt][2], al[mt][3],
                             bh0[nt], bh1[nt]);
                }
        }
    }

    // ---- node_out epilogue ----
    {
        const int rr = lane >> 2;
        const int cc = (lane & 3) * 2;
#pragma unroll
        for (int mt = 0; mt < 2; mt++) {
            long r = tileRow + w * 32 + mt * 16 + rr;
#pragma unroll
            for (int nt = 0; nt < 4; nt++) {
                float* dd = acc[mt][nt];
                int c0 = nt * 8 + cc;
                *(float2*)(node_out + r * HN + c0) = make_float2(dd[0], dd[1]);
                *(float2*)(node_out + (r + 8) * HN + c0) = make_float2(dd[2], dd[3]);
            }
        }
    }

    // ---- graph head: stage Wg (64 KB) into dead X/W smem, then dot ----
    __syncthreads();
    {
        const float4* Wg4 = (const float4*)Wg;
        float4* Wd = (float4*)smem;          // overlays buffers + WH/WL (66.5 KB)
#pragma unroll
        for (int i = 0; i < 32; i++) Wd[t + 128 * i] = Wg4[t + 128 * i];
    }
    __syncthreads();
    {
        const float* Wgs = (const float*)smem;   // [256 d][64 j]
        const int g = t >> 6;
        const int j = t & 63;
        const float* gsg = gsum + g * 256;
        float s = 0.f;
#pragma unroll 8
        for (int d = 0; d < 256; d++)
            s += gsg[d] * Wgs[d * 64 + j];
        graph_out[(blockIdx.x * 2 + g) * HG + j] = s * (1.0f / 64.0f) + __ldg(bg + j);
    }
}

// ---------------------------------------------------------------------------
extern "C" void kernel_launch(void* const* d_in, const int* in_sizes, int n_in,
                              void* d_out, int out_size) {
    const float* X  = (const float*)d_in[0];
    // d_in[1] = batch (int32): 64 consecutive nodes per graph, implicit
    const float* Wg = (const float*)d_in[2];
    const float* bg = (const float*)d_in[3];
    const float* Wn = (const float*)d_in[4];
    float* out = (float*)d_out;
    (void)in_sizes; (void)n_in; (void)out_size;

    cudaFuncSetAttribute(k_fused, cudaFuncAttributeMaxDynamicSharedMemorySize, SMEM_BYTES);

    // output layout: graph_out [2048*64] first, then node_out [131072*32]
    k_fused<<<1024, 128, SMEM_BYTES>>>(X, Wn, Wg, bg, out, out + NUM_GRAPHS * HG);
}

// round 8
// speedup vs baseline: 1.1192x; 1.0866x over previous
#include <cuda_runtime.h>
#include <cuda_bf16.h>
#include <cstdint>

#define NUM_GRAPHS 2048
#define DIM 256
#define HN 32
#define HG 64

typedef unsigned int u32;
typedef unsigned long long u64;

// ---- smem layout (bytes) ----
// X buffers: 2 x { hi 16384, lo 16384 }  [256 r][32 k] bf16, row-pair swizzle
#define SM_BUF(b)  ((u32)(b) * 32768u)
#define SM_WH 65536u      // W^T hi [32 n][264 k] bf16 pad8  (16896)
#define SM_WL 82432u      // W^T lo                           (16896)
#define SM_SCR0 99328u    // scratch buf0: 256 x float4       (4096)
#define SM_SCR1 103424u   // scratch buf1                     (4096)
#define SM_GS 107520u     // graph sums 4 x 256 f32           (4096)
#define SMEM_BYTES 111616
#define WROW 528          // bytes per W^T row (264 bf16)

__device__ __forceinline__ u32 smem_u32(const void* p) {
    u32 a;
    asm("{ .reg .u64 t; cvta.to.shared.u64 t, %1; cvt.u32.u64 %0, t; }" : "=r"(a) : "l"(p));
    return a;
}
__device__ __forceinline__ void ldsm4(u32& r0, u32& r1, u32& r2, u32& r3, u32 a) {
    asm volatile("ldmatrix.sync.aligned.m8n8.x4.shared.b16 {%0,%1,%2,%3}, [%4];"
        : "=r"(r0), "=r"(r1), "=r"(r2), "=r"(r3) : "r"(a));
}
__device__ __forceinline__ void mma16816(float* d, u32 a0, u32 a1, u32 a2, u32 a3,
                                         u32 b0, u32 b1) {
    asm volatile("mma.sync.aligned.m16n8k16.row.col.f32.bf16.bf16.f32 "
        "{%0,%1,%2,%3}, {%4,%5,%6,%7}, {%8,%9}, {%0,%1,%2,%3};"
        : "+f"(d[0]), "+f"(d[1]), "+f"(d[2]), "+f"(d[3])
        : "r"(a0), "r"(a1), "r"(a2), "r"(a3), "r"(b0), "r"(b1));
}
__device__ __forceinline__ u32 bits2(__nv_bfloat162 v) {
    u32 r; __builtin_memcpy(&r, &v, 4); return r;
}
// hi = truncate-to-bf16 (exact, PRMT-packed); lo = rn_bf16(x - hi)
__device__ __forceinline__ void split2(float x0, float x1, u32& hp, u32& lp) {
    u32 u0 = __float_as_uint(x0), u1 = __float_as_uint(x1);
    asm("prmt.b32 %0, %1, %2, 0x7632;" : "=r"(hp) : "r"(u0), "r"(u1));
    float h0 = __uint_as_float(u0 & 0xFFFF0000u);
    float h1 = __uint_as_float(u1 & 0xFFFF0000u);
    lp = bits2(__float22bfloat162_rn(make_float2(x0 - h0, x1 - h1)));
}
// packed f32x2 add (1 instr for 2 adds — issue-count saver)
__device__ __forceinline__ void add2(u64& d, u64 a) {
    asm("add.rn.f32x2 %0, %0, %1;" : "+l"(d) : "l"(a));
}

// ---------------------------------------------------------------------------
// Fused kernel: CTA = 256 nodes = 4 graphs. grid 512, 256 threads, 2 CTAs/SM.
// K pipelined in 8 chunks of 32 with double-buffered X smem:
//   stage(ch) -> LDG(ch+1) -> sync -> reduce -> MMA(ch)
// Per warp: M=32 (2 m16), N=32, bf16 hi/lo 3-term mma.sync.
// ---------------------------------------------------------------------------
__global__ __launch_bounds__(256, 2) void k_fused(
    const float* __restrict__ X, const float* __restrict__ Wn,
    const float* __restrict__ Wg, const float* __restrict__ bg,
    float* __restrict__ graph_out, float* __restrict__ node_out)
{
    extern __shared__ char smem[];
    const u32 sbase = smem_u32(smem);
    float4* scr[2] = { (float4*)(smem + SM_SCR0), (float4*)(smem + SM_SCR1) };
    float*  gsum = (float*)(smem + SM_GS);

    const int t = threadIdx.x;
    const int w = t >> 5;
    const int lane = t & 31;
    const long tileRow = (long)blockIdx.x * 256;

    // ---- stage W^T hi/lo : Wn[256][32] f32 -> [n][264k] bf16 (pad rows) ----
    {
        const float4* W4 = (const float4*)Wn;
#pragma unroll
        for (int i = 0; i < 8; i++) {
            int idx = t + 256 * i;       // 2048 float4
            float4 v = W4[idx];
            int d = idx >> 3;            // k dim 0..255
            int n0 = (idx & 7) * 4;
            float vv[4] = {v.x, v.y, v.z, v.w};
#pragma unroll
            for (int j = 0; j < 4; j++) {
                __nv_bfloat16 h = __float2bfloat16_rz(vv[j]);   // truncation (matches X split)
                float rsd = vv[j] - __bfloat162float(h);
                __nv_bfloat16 l = __float2bfloat16_rn(rsd);
                u32 off = (u32)(n0 + j) * WROW + (u32)d * 2;
                *(__nv_bfloat16*)(smem + SM_WH + off) = h;
                *(__nv_bfloat16*)(smem + SM_WL + off) = l;
            }
        }
    }

    // ---- fragment address precompute ----
    const int aq = lane >> 3;
    const int ai = lane & 7;
    // A row-pair packed layout: addr = (r>>1)*128 + (r&1)*64 + kq*16,
    //   swizzled by key ((r>>1)&7)<<4
    u32 rb[2];
#pragma unroll
    for (int mt = 0; mt < 2; mt++) {
        int r = w * 32 + mt * 16 + ((aq & 1) ? 8 : 0) + ai;
        rb[mt] = ((u32)(r >> 1) * 128u + (u32)(r & 1) * 64u) ^ ((((u32)r >> 1) & 7u) << 4);
    }
    const u32 kqsel = (u32)(aq >> 1) << 4;
    const u32 bbase = (u32)(aq * 8 + ai) * WROW;

    float acc[2][4][4];
#pragma unroll
    for (int mt = 0; mt < 2; mt++)
#pragma unroll
        for (int nt = 0; nt < 4; nt++)
#pragma unroll
            for (int e = 0; e < 4; e++) acc[mt][nt][e] = 0.f;

    // ---- staging geometry: thread's 8 rows all in ONE graph ----
    // t = (g:2)(rs8:3)(c4:3): rows r_i = g*64 + rs8 + 8*i (i=0..7), col quad c4
    const int c4  = t & 7;
    const int rs8 = (t >> 3) & 7;
    const int g   = t >> 6;
    const int r0  = g * 64 + rs8;
    const float4* xp = (const float4*)X + (tileRow + r0) * 64 + c4;
    // STS offset: p_i = (r0>>1) + 4i ; key_i = key0 ^ (4*(i&1)) ; +4 mod 8 == ^4
    const u32 sts_base = (((u32)(r0 >> 1) * 128u + (u32)(r0 & 1) * 64u)
                          ^ ((((u32)r0 >> 1) & 7u) << 4)) ^ ((u32)c4 << 3);

    // prologue: LDG chunk 0 (rows step 8 -> 8*64 float4 = 512)
    float4 v[8];
#pragma unroll
    for (int i = 0; i < 8; i++) v[i] = xp[i * 512];

#pragma unroll 1
    for (int ch = 0; ch < 8; ch++) {
        const int b = ch & 1;
        const u32 hbuf = SM_BUF(b);

        // ---- convert + STS chunk ch; packed fp32 graph partial ----
        u64 pxy = 0ULL, pzw = 0ULL;
#pragma unroll
        for (int i = 0; i < 8; i++) {
            uint2 hp, lp;
            split2(v[i].x, v[i].y, hp.x, lp.x);
            split2(v[i].z, v[i].w, hp.y, lp.y);
            u32 off = (sts_base + (u32)i * 512u) ^ (((u32)i & 1u) << 6);
            *(uint2*)(smem + hbuf + off) = hp;
            *(uint2*)(smem + hbuf + 16384u + off) = lp;
            u64 a, bb;
            __builtin_memcpy(&a, &v[i].x, 8);
            __builtin_memcpy(&bb, &v[i].z, 8);
            add2(pxy, a);
            add2(pzw, bb);
        }
        {
            float4 p;
            __builtin_memcpy(&p.x, &pxy, 8);
            __builtin_memcpy(&p.z, &pzw, 8);
            scr[b][t] = p;
        }

        // ---- issue LDGs for chunk ch+1 (latency hidden by sync + MMA) ----
        if (ch < 7) {
#pragma unroll
            for (int i = 0; i < 8; i++) v[i] = xp[i * 512 + (ch + 1) * 8];
        }

        __syncthreads();   // STS(ch) visible; buffers alternate so MMA(ch-1) safe

        // ---- graph column-sum reduce (32 threads, overlaps others' MMA) ----
        if (t < 32) {
            int gg = t >> 3, cc = t & 7;
            float4 a = scr[b][gg * 64 + cc];
#pragma unroll
            for (int j = 1; j < 8; j++) {
                float4 x2 = scr[b][gg * 64 + j * 8 + cc];
                a.x += x2.x; a.y += x2.y; a.z += x2.z; a.w += x2.w;
            }
            *(float4*)&gsum[gg * 256 + ch * 32 + cc * 4] = a;
        }

        // ---- MMA on buffer b: 2 k16-steps ----
#pragma unroll
        for (int ks = 0; ks < 2; ks++) {
            const u32 kx = ((u32)ks << 5) ^ kqsel;
            u32 ah[2][4], al[2][4];
            ldsm4(ah[0][0], ah[0][1], ah[0][2], ah[0][3], sbase + hbuf + (rb[0] ^ kx));
            ldsm4(ah[1][0], ah[1][1], ah[1][2], ah[1][3], sbase + hbuf + (rb[1] ^ kx));
            ldsm4(al[0][0], al[0][1], al[0][2], al[0][3], sbase + hbuf + 16384u + (rb[0] ^ kx));
            ldsm4(al[1][0], al[1][1], al[1][2], al[1][3], sbase + hbuf + 16384u + (rb[1] ^ kx));

            const u32 bko = (u32)(ch * 2 + ks) << 5;   // k16-step * 32 bytes
            u32 bh0[4], bh1[4], bl0[4], bl1[4];
            ldsm4(bh0[0], bh0[1], bh0[2], bh0[3], sbase + SM_WH + bbase + bko);
            ldsm4(bh1[0], bh1[1], bh1[2], bh1[3], sbase + SM_WH + bbase + bko + 16);
            ldsm4(bl0[0], bl0[1], bl0[2], bl0[3], sbase + SM_WL + bbase + bko);
            ldsm4(bl1[0], bl1[1], bl1[2], bl1[3], sbase + SM_WL + bbase + bko + 16);

#pragma unroll
            for (int mt = 0; mt < 2; mt++)
#pragma unroll
                for (int nt = 0; nt < 4; nt++) {
                    mma16816(acc[mt][nt], ah[mt][0], ah[mt][1], ah[mt][2], ah[mt][3],
                             bh0[nt], bh1[nt]);
                    mma16816(acc[mt][nt], ah[mt][0], ah[mt][1], ah[mt][2], ah[mt][3],
                             bl0[nt], bl1[nt]);
                    mma16816(acc[mt][nt], al[mt][0], al[mt][1], al[mt][2], al[mt][3],
                             bh0[nt], bh1[nt]);
                }
        }
    }

    // ---- node_out epilogue ----
    {
        const int rr = lane >> 2;
        const int cc = (lane & 3) * 2;
#pragma unroll
        for (int mt = 0; mt < 2; mt++) {
            long r = tileRow + w * 32 + mt * 16 + rr;
#pragma unroll
            for (int nt = 0; nt < 4; nt++) {
                float* dd = acc[mt][nt];
                int c0 = nt * 8 + cc;
                *(float2*)(node_out + r * HN + c0) = make_float2(dd[0], dd[1]);
                *(float2*)(node_out + (r + 8) * HN + c0) = make_float2(dd[2], dd[3]);
            }
        }
    }

    // ---- graph head: stage Wg (64 KB) into dead X smem, then dot ----
    __syncthreads();
    {
        const float4* Wg4 = (const float4*)Wg;
        float4* Wd = (float4*)smem;          // overlays X buffers (64 KB avail)
#pragma unroll
        for (int i = 0; i < 16; i++) Wd[t + 256 * i] = Wg4[t + 256 * i];
    }
    __syncthreads();
    {
        const float* Wgs = (const float*)smem;   // [256 d][64 j]
        const int gg = t >> 6;
        const int j = t & 63;
        const float* gsg = gsum + gg * 256;
        float s = 0.f;
#pragma unroll 8
        for (int d = 0; d < 256; d++)
            s += gsg[d] * Wgs[d * 64 + j];
        graph_out[(blockIdx.x * 4 + gg) * HG + j] = s * (1.0f / 64.0f) + __ldg(bg + j);
    }
}

// ---------------------------------------------------------------------------
extern "C" void kernel_launch(void* const* d_in, const int* in_sizes, int n_in,
                              void* d_out, int out_size) {
    const float* X  = (const float*)d_in[0];
    // d_in[1] = batch (int32): 64 consecutive nodes per graph, implicit
    const float* Wg = (const float*)d_in[2];
    const float* bg = (const float*)d_in[3];
    const float* Wn = (const float*)d_in[4];
    float* out = (float*)d_out;
    (void)in_sizes; (void)n_in; (void)out_size;

    cudaFuncSetAttribute(k_fused, cudaFuncAttributeMaxDynamicSharedMemorySize, SMEM_BYTES);

    // output layout: graph_out [2048*64] first, then node_out [131072*32]
    k_fused<<<512, 256, SMEM_BYTES>>>(X, Wn, Wg, bg, out, out + NUM_GRAPHS * HG);
}